// round 7
// baseline (speedup 1.0000x reference)
#include <cuda_runtime.h>
#include <cuda_bf16.h>
#include <stdint.h>

// WeightsDropout: per row of [8192,1,4096] f32, zero the 2048 smallest
// (stable-argsort tie-break by index), softmax over survivors.
//
// One CTA (512 thr) per row, 8 elems/thread in registers, 4 CTAs/SM.
// 1024 fine bins over [0.46875, 0.53125) (boundary ~0.5 +- 4 sigma).
// If the boundary bin holds exactly 1 element (P~0.78), rstar==0 and
// keep = (bin >= bstar) -- no key, no gather. Otherwise gather that bin's
// few keys (bits<<12|idx == stable-sort order), rank them once, and use a
// single (val,idx) compare. Window miss / overflow -> exact radix-select.

namespace {

constexpr int N       = 4096;
constexpr int KDROP   = 2048;
constexpr int THREADS = 512;
constexpr int VEC     = 2;                // float4 per thread (8 elems)
constexpr int NWARP   = THREADS / 32;     // 16
constexpr int NB      = 1024;
constexpr int C2_CAP  = 32;

constexpr float WSC   = 16384.0f;         // 1024 bins over [0.46875, 0.53125)
constexpr float WOFF  = -7680.0f;         // -0.46875 * 16384
constexpr float LOG2E = 1.4426950408889634f;

__device__ __forceinline__ unsigned u_of_bits(unsigned b) {
    return (b & 0x80000000u) ? ~b : (b | 0x80000000u);
}

__global__ __launch_bounds__(THREADS, 4)
void wdrop_kernel(const float* __restrict__ in, float* __restrict__ out)
{
    __shared__ unsigned hist[NB];
    __shared__ unsigned long long cand2[C2_CAP];
    __shared__ unsigned m_n;
    __shared__ float    s_redf[NWARP];
    __shared__ unsigned s_redu[NWARP];
    __shared__ unsigned s_bin, s_rank, s_cnt, s_found;
    __shared__ float    s_max, s_inv;
    __shared__ unsigned long long s_thr;
    __shared__ unsigned long long s_pref;
    __shared__ unsigned s_rrem;

    const int t    = threadIdx.x;
    const int lane = t & 31;
    const int warp = t >> 5;

    const long long row = blockIdx.x;
    const float* __restrict__ inp  = in  + row * (long long)N;
    float*       __restrict__ outp = out + row * (long long)N;

    hist[t]           = 0u;
    hist[t + THREADS] = 0u;
    if (t == 0) { m_n = 0u; s_found = 0u; }
    __syncthreads();                        // B1: init

    // ---- pass 1: load, max, below-count, fine histogram ----
    float4 xs[VEC];
#pragma unroll
    for (int j = 0; j < VEC; j++)
        xs[j] = __ldcs(reinterpret_cast<const float4*>(inp) + t + THREADS * j);

    float vmax = 0.0f;                      // inputs positive
    unsigned below = 0;
#pragma unroll
    for (int j = 0; j < VEC; j++) {
        float vv[4] = {xs[j].x, xs[j].y, xs[j].z, xs[j].w};
#pragma unroll
        for (int c = 0; c < 4; c++) {
            float val = vv[c];
            vmax = fmaxf(vmax, val);
            int b = __float2int_rd(fmaf(val, WSC, WOFF));
            below += (b < 0) ? 1u : 0u;
            if ((unsigned)b < (unsigned)NB) atomicAdd(&hist[b], 1u);
        }
    }
#pragma unroll
    for (int o = 16; o; o >>= 1) {
        vmax   = fmaxf(vmax, __shfl_xor_sync(0xffffffffu, vmax, o));
        below += __shfl_xor_sync(0xffffffffu, below, o);
    }
    if (lane == 0) { s_redf[warp] = vmax; s_redu[warp] = below; }
    __syncthreads();                        // B2: hist + partials ready

    // ---- warp 0: combine reductions; scan 1024 bins ----
    if (warp == 0) {
        float    m = (lane < NWARP) ? s_redf[lane] : 0.0f;
        unsigned b = (lane < NWARP) ? s_redu[lane] : 0u;
#pragma unroll
        for (int o = 16; o; o >>= 1) {
            m  = fmaxf(m, __shfl_xor_sync(0xffffffffu, m, o));
            b += __shfl_xor_sync(0xffffffffu, b, o);
        }
        if (lane == 0) s_max = m;

        unsigned cb[32]; unsigned sum = 0;
#pragma unroll
        for (int i = 0; i < 32; i++) { cb[i] = hist[lane * 32 + i]; sum += cb[i]; }
        unsigned inc = sum;
#pragma unroll
        for (int o = 1; o < 32; o <<= 1) {
            unsigned nn = __shfl_up_sync(0xffffffffu, inc, o);
            if (lane >= o) inc += nn;
        }
        unsigned c = b + inc - sum;
#pragma unroll
        for (int i = 0; i < 32; i++) {
            unsigned cc = cb[i];
            if (c <= (unsigned)KDROP && (unsigned)KDROP < c + cc) {
                s_bin   = (unsigned)(lane * 32 + i);
                s_rank  = (unsigned)KDROP - c;
                s_cnt   = cc;
                s_found = 1u;
            }
            c += cc;
        }
    }
    __syncthreads();                        // B3: bstar/rank/cnt ready

    const unsigned found = s_found;
    const unsigned bstar = s_bin;
    const unsigned cnt   = s_cnt;
    const float    mC    = -s_max * LOG2E;

    bool fast = (found && cnt == 1u);       // uniform across CTA
    unsigned long long thr = 0ull;
    bool have_thr = fast;

    if (found && !fast) {
        // ---- rare: gather boundary-bin keys, rank once ----
#pragma unroll
        for (int j = 0; j < VEC; j++) {
            float vv[4] = {xs[j].x, xs[j].y, xs[j].z, xs[j].w};
#pragma unroll
            for (int c = 0; c < 4; c++) {
                float val = vv[c];
                int b = __float2int_rd(fmaf(val, WSC, WOFF));
                if ((unsigned)b == bstar) {
                    unsigned p = atomicAdd(&m_n, 1u);
                    if (p < (unsigned)C2_CAP) {
                        unsigned idx = (unsigned)(4 * (t + THREADS * j) + c);
                        cand2[p] = ((unsigned long long)__float_as_uint(val) << 12)
                                 | (unsigned long long)idx;
                    }
                }
            }
        }
        __syncthreads();
        if (warp == 0) {
            unsigned mn = m_n, rstar = s_rank;
            if (mn <= (unsigned)C2_CAP && lane < mn) {
                unsigned long long k = cand2[lane];
                unsigned rk = 0;
                for (unsigned i = 0; i < mn; i++) rk += (cand2[i] < k) ? 1u : 0u;
                if (rk == rstar) s_thr = k;
            }
        }
        __syncthreads();
        have_thr = (m_n <= (unsigned)C2_CAP);
        thr = s_thr;
    }

    // ---- cold exact fallback: radix-select on monotone 44-bit keys ----
    if (!have_thr) {
        if (t == 0) { s_pref = 0ull; s_rrem = (unsigned)KDROP; }
        const int shifts[6] = {36, 28, 20, 12, 6, 0};
        const int widths[6] = {256, 256, 256, 256, 64, 64};
        unsigned long long mask = 0ull;
#pragma unroll 1
        for (int L = 0; L < 6; L++) {
            if (t < widths[L]) hist[t] = 0u;
            __syncthreads();
            unsigned long long pref = s_pref;
#pragma unroll 1
            for (int j = 0; j < VEC; j++) {
                float vv[4] = {xs[j].x, xs[j].y, xs[j].z, xs[j].w};
#pragma unroll 1
                for (int c = 0; c < 4; c++) {
                    unsigned idx = (unsigned)(4 * (t + THREADS * j) + c);
                    unsigned long long K =
                        ((unsigned long long)u_of_bits(__float_as_uint(vv[c])) << 12)
                      | (unsigned long long)idx;
                    if ((K & mask) == pref)
                        atomicAdd(&hist[(unsigned)(K >> shifts[L]) & (unsigned)(widths[L] - 1)], 1u);
                }
            }
            __syncthreads();
            if (t == 0) {
                unsigned r = s_rrem, acc = 0;
                for (int i = 0; i < widths[L]; i++) {
                    unsigned cc = hist[i];
                    if (acc <= r && r < acc + cc) {
                        s_pref = pref | ((unsigned long long)i << shifts[L]);
                        s_rrem = r - acc;
                        break;
                    }
                    acc += cc;
                }
            }
            mask |= (unsigned long long)(widths[L] - 1) << shifts[L];
            __syncthreads();
        }
        if (t == 0) {
            unsigned long long pref = s_pref;
            unsigned uu = (unsigned)(pref >> 12);
            unsigned bits = (uu & 0x80000000u) ? (uu ^ 0x80000000u) : ~uu;
            s_thr = ((unsigned long long)bits << 12) | (pref & 0xFFFull);
        }
        __syncthreads();
        thr = s_thr;
        fast = false;
    }

    // ---- pass 3: keep + exp2 + sum ----
    float lsum = 0.0f;
    if (fast) {
        // cnt==1 => rstar==0 => keep iff bin >= bstar
        const int bs = (int)bstar;
#pragma unroll
        for (int j = 0; j < VEC; j++) {
            float vv[4] = {xs[j].x, xs[j].y, xs[j].z, xs[j].w};
            float ee[4];
#pragma unroll
            for (int c = 0; c < 4; c++) {
                float val = vv[c];
                int b = __float2int_rd(fmaf(val, WSC, WOFF));
                float e = (b >= bs) ? exp2f(fmaf(val, LOG2E, mC)) : 0.0f;
                ee[c] = e;
                lsum += e;
            }
            xs[j].x = ee[0]; xs[j].y = ee[1]; xs[j].z = ee[2]; xs[j].w = ee[3];
        }
    } else {
        const float    thr_val = __uint_as_float((unsigned)(thr >> 12));
        const unsigned thr_idx = (unsigned)(thr & 0xFFFull);
#pragma unroll
        for (int j = 0; j < VEC; j++) {
            float vv[4] = {xs[j].x, xs[j].y, xs[j].z, xs[j].w};
            float ee[4];
#pragma unroll
            for (int c = 0; c < 4; c++) {
                float val = vv[c];
                unsigned idx = (unsigned)(4 * (t + THREADS * j) + c);
                bool keep = (val > thr_val) || (val == thr_val && idx >= thr_idx);
                float e = keep ? exp2f(fmaf(val, LOG2E, mC)) : 0.0f;
                ee[c] = e;
                lsum += e;
            }
            xs[j].x = ee[0]; xs[j].y = ee[1]; xs[j].z = ee[2]; xs[j].w = ee[3];
        }
    }
#pragma unroll
    for (int o = 16; o; o >>= 1) lsum += __shfl_xor_sync(0xffffffffu, lsum, o);
    if (lane == 0) s_redf[warp] = lsum;
    __syncthreads();                        // B4: partials ready
    if (warp == 0) {
        float s = (lane < NWARP) ? s_redf[lane] : 0.0f;
#pragma unroll
        for (int o = 16; o; o >>= 1) s += __shfl_xor_sync(0xffffffffu, s, o);
        if (lane == 0) s_inv = 1.0f / s;
    }
    __syncthreads();                        // B5: inv ready
    const float inv = s_inv;

    // ---- scaled streaming store ----
#pragma unroll
    for (int j = 0; j < VEC; j++) {
        float4 o4 = {xs[j].x * inv, xs[j].y * inv, xs[j].z * inv, xs[j].w * inv};
        __stcs(reinterpret_cast<float4*>(outp) + t + THREADS * j, o4);
    }
}

} // anonymous namespace

extern "C" void kernel_launch(void* const* d_in, const int* in_sizes, int n_in,
                              void* d_out, int out_size)
{
    (void)n_in; (void)in_sizes;
    const float* w = (const float*)d_in[0];
    float* outp = (float*)d_out;
    int rows = out_size / N;            // 8192
    wdrop_kernel<<<rows, THREADS>>>(w, outp);
}

// round 8
// speedup vs baseline: 1.2626x; 1.2626x over previous
#include <cuda_runtime.h>
#include <cuda_bf16.h>
#include <stdint.h>

// WeightsDropout: per row of [8192,1,4096] f32, zero the 2048 smallest
// (stable-argsort tie-break by index), softmax over survivors.
//
// One CTA (512 thr) per row, 8 elems/thread in registers, 3 CTAs/SM.
// 512 fine bins over [0.46875, 0.53125) (rank-2048 boundary ~0.5 +- 4sigma).
// If the boundary bin holds exactly 1 element (~77% of rows): rstar==0,
// no ties possible -> keep = (bin >= bstar); no gather, no key compare.
// Else: gather that bin's few keys (bits<<12|idx == stable-sort order),
// rank once, keep via single (val,idx) compare. Window miss / overflow ->
// exact 6-level radix-select on monotone 44-bit keys (cold).

namespace {

constexpr int N       = 4096;
constexpr int KDROP   = 2048;
constexpr int THREADS = 512;
constexpr int VEC     = 2;                // float4 per thread (8 elems)
constexpr int NWARP   = THREADS / 32;     // 16
constexpr int NB      = 512;
constexpr int C2_CAP  = 32;

constexpr float WSC   = 8192.0f;          // 512 bins over [0.46875, 0.53125)
constexpr float WOFF  = -3840.0f;         // -0.46875 * 8192
constexpr float LOG2E = 1.4426950408889634f;

__device__ __forceinline__ unsigned u_of_bits(unsigned b) {
    return (b & 0x80000000u) ? ~b : (b | 0x80000000u);
}

__global__ __launch_bounds__(THREADS, 3)
void wdrop_kernel(const float* __restrict__ in, float* __restrict__ out)
{
    __shared__ unsigned hist[NB];
    __shared__ unsigned long long cand2[C2_CAP];
    __shared__ unsigned m_n;
    __shared__ float    s_redf[NWARP];
    __shared__ unsigned s_redu[NWARP];
    __shared__ unsigned s_bin, s_rank, s_cnt, s_found;
    __shared__ float    s_max, s_inv;
    __shared__ unsigned long long s_thr;
    __shared__ unsigned long long s_pref;
    __shared__ unsigned s_rrem;

    const int t    = threadIdx.x;
    const int lane = t & 31;
    const int warp = t >> 5;

    const long long row = blockIdx.x;
    const float4* __restrict__ in4  = reinterpret_cast<const float4*>(in  + row * (long long)N);
    float4*       __restrict__ out4 = reinterpret_cast<float4*>      (out + row * (long long)N);

    hist[t] = 0u;                          // NB == THREADS
    if (t == 0) { m_n = 0u; s_found = 0u; }
    __syncthreads();                       // B1: init

    // ---- pass 1: load, max, below-count, window histogram ----
    float4 xs[VEC];
#pragma unroll
    for (int j = 0; j < VEC; j++) xs[j] = in4[t + THREADS * j];

    float vmax = 0.0f;                     // inputs positive
    unsigned below = 0;
#pragma unroll
    for (int j = 0; j < VEC; j++) {
        float vv[4] = {xs[j].x, xs[j].y, xs[j].z, xs[j].w};
#pragma unroll
        for (int c = 0; c < 4; c++) {
            float val = vv[c];
            vmax = fmaxf(vmax, val);
            int b = __float2int_rd(fmaf(val, WSC, WOFF));
            below += (b < 0) ? 1u : 0u;
            if ((unsigned)b < (unsigned)NB) atomicAdd(&hist[b], 1u);
        }
    }
#pragma unroll
    for (int o = 16; o; o >>= 1) {
        vmax   = fmaxf(vmax, __shfl_xor_sync(0xffffffffu, vmax, o));
        below += __shfl_xor_sync(0xffffffffu, below, o);
    }
    if (lane == 0) { s_redf[warp] = vmax; s_redu[warp] = below; }
    __syncthreads();                       // B2: hist + partials ready

    // ---- warp 0: combine reductions; scan 512 bins (two smem sweeps) ----
    if (warp == 0) {
        float    m = (lane < NWARP) ? s_redf[lane] : 0.0f;
        unsigned b = (lane < NWARP) ? s_redu[lane] : 0u;
#pragma unroll
        for (int o = 16; o; o >>= 1) {
            m  = fmaxf(m, __shfl_xor_sync(0xffffffffu, m, o));
            b += __shfl_xor_sync(0xffffffffu, b, o);
        }
        if (lane == 0) s_max = m;

        unsigned sum = 0;
#pragma unroll
        for (int i = 0; i < 16; i++) sum += hist[lane * 16 + i];
        unsigned inc = sum;
#pragma unroll
        for (int o = 1; o < 32; o <<= 1) {
            unsigned nn = __shfl_up_sync(0xffffffffu, inc, o);
            if (lane >= o) inc += nn;
        }
        unsigned c = b + inc - sum;
#pragma unroll
        for (int i = 0; i < 16; i++) {
            unsigned cc = hist[lane * 16 + i];
            if (c <= (unsigned)KDROP && (unsigned)KDROP < c + cc) {
                s_bin   = (unsigned)(lane * 16 + i);
                s_rank  = (unsigned)KDROP - c;
                s_cnt   = cc;
                s_found = 1u;
            }
            c += cc;
        }
    }
    __syncthreads();                       // B3: bstar/rank/cnt ready

    const unsigned found = s_found;
    const unsigned bstar = s_bin;
    const unsigned cnt   = s_cnt;
    const float    mC    = -s_max * LOG2E;

    bool fast = (found && cnt == 1u);      // uniform across CTA
    unsigned long long thr = 0ull;
    bool have_thr = fast;

    if (found && !fast) {
        // ---- slow (~23%): gather boundary-bin keys, rank once ----
#pragma unroll
        for (int j = 0; j < VEC; j++) {
            float vv[4] = {xs[j].x, xs[j].y, xs[j].z, xs[j].w};
#pragma unroll
            for (int c = 0; c < 4; c++) {
                float val = vv[c];
                int b = __float2int_rd(fmaf(val, WSC, WOFF));
                if ((unsigned)b == bstar) {
                    unsigned p = atomicAdd(&m_n, 1u);
                    if (p < (unsigned)C2_CAP) {
                        unsigned idx = (unsigned)(4 * (t + THREADS * j) + c);
                        cand2[p] = ((unsigned long long)__float_as_uint(val) << 12)
                                 | (unsigned long long)idx;
                    }
                }
            }
        }
        __syncthreads();
        if (warp == 0) {
            unsigned mn = m_n, rstar = s_rank;
            if (mn <= (unsigned)C2_CAP && lane < mn) {
                unsigned long long k = cand2[lane];
                unsigned rk = 0;
                for (unsigned i = 0; i < mn; i++) rk += (cand2[i] < k) ? 1u : 0u;
                if (rk == rstar) s_thr = k;
            }
        }
        __syncthreads();
        have_thr = (m_n <= (unsigned)C2_CAP);
        thr = s_thr;
    }

    // ---- cold exact fallback: radix-select on monotone 44-bit keys ----
    if (!have_thr) {
        if (t == 0) { s_pref = 0ull; s_rrem = (unsigned)KDROP; }
        const int shifts[6] = {36, 28, 20, 12, 6, 0};
        const int widths[6] = {256, 256, 256, 256, 64, 64};
        unsigned long long mask = 0ull;
#pragma unroll 1
        for (int L = 0; L < 6; L++) {
            if (t < widths[L]) hist[t] = 0u;
            __syncthreads();
            unsigned long long pref = s_pref;
#pragma unroll 1
            for (int j = 0; j < VEC; j++) {
                float vv[4] = {xs[j].x, xs[j].y, xs[j].z, xs[j].w};
#pragma unroll 1
                for (int c = 0; c < 4; c++) {
                    unsigned idx = (unsigned)(4 * (t + THREADS * j) + c);
                    unsigned long long K =
                        ((unsigned long long)u_of_bits(__float_as_uint(vv[c])) << 12)
                      | (unsigned long long)idx;
                    if ((K & mask) == pref)
                        atomicAdd(&hist[(unsigned)(K >> shifts[L]) & (unsigned)(widths[L] - 1)], 1u);
                }
            }
            __syncthreads();
            if (t == 0) {
                unsigned r = s_rrem, acc = 0;
                for (int i = 0; i < widths[L]; i++) {
                    unsigned cc = hist[i];
                    if (acc <= r && r < acc + cc) {
                        s_pref = pref | ((unsigned long long)i << shifts[L]);
                        s_rrem = r - acc;
                        break;
                    }
                    acc += cc;
                }
            }
            mask |= (unsigned long long)(widths[L] - 1) << shifts[L];
            __syncthreads();
        }
        if (t == 0) {
            unsigned long long pref = s_pref;
            unsigned uu = (unsigned)(pref >> 12);
            unsigned bits = (uu & 0x80000000u) ? (uu ^ 0x80000000u) : ~uu;
            s_thr = ((unsigned long long)bits << 12) | (pref & 0xFFFull);
        }
        __syncthreads();
        thr = s_thr;
        fast = false;
    }

    // ---- pass 3: keep + exp2 + sum ----
    float lsum = 0.0f;
    if (fast) {
        // cnt==1 => rstar==0, no ties => keep iff bin >= bstar
        const int bs = (int)bstar;
#pragma unroll
        for (int j = 0; j < VEC; j++) {
            float vv[4] = {xs[j].x, xs[j].y, xs[j].z, xs[j].w};
            float ee[4];
#pragma unroll
            for (int c = 0; c < 4; c++) {
                float val = vv[c];
                int b = __float2int_rd(fmaf(val, WSC, WOFF));
                float e = (b >= bs) ? exp2f(fmaf(val, LOG2E, mC)) : 0.0f;
                ee[c] = e;
                lsum += e;
            }
            xs[j].x = ee[0]; xs[j].y = ee[1]; xs[j].z = ee[2]; xs[j].w = ee[3];
        }
    } else {
        const float    thr_val = __uint_as_float((unsigned)(thr >> 12));
        const unsigned thr_idx = (unsigned)(thr & 0xFFFull);
#pragma unroll
        for (int j = 0; j < VEC; j++) {
            float vv[4] = {xs[j].x, xs[j].y, xs[j].z, xs[j].w};
            float ee[4];
#pragma unroll
            for (int c = 0; c < 4; c++) {
                float val = vv[c];
                unsigned idx = (unsigned)(4 * (t + THREADS * j) + c);
                bool keep = (val > thr_val) || (val == thr_val && idx >= thr_idx);
                float e = keep ? exp2f(fmaf(val, LOG2E, mC)) : 0.0f;
                ee[c] = e;
                lsum += e;
            }
            xs[j].x = ee[0]; xs[j].y = ee[1]; xs[j].z = ee[2]; xs[j].w = ee[3];
        }
    }
#pragma unroll
    for (int o = 16; o; o >>= 1) lsum += __shfl_xor_sync(0xffffffffu, lsum, o);
    if (lane == 0) s_redf[warp] = lsum;
    __syncthreads();                       // B4: partials ready
    if (warp == 0) {
        float s = (lane < NWARP) ? s_redf[lane] : 0.0f;
#pragma unroll
        for (int o = 16; o; o >>= 1) s += __shfl_xor_sync(0xffffffffu, s, o);
        if (lane == 0) s_inv = 1.0f / s;
    }
    __syncthreads();                       // B5: inv ready
    const float inv = s_inv;

    // ---- scaled store from registers ----
#pragma unroll
    for (int j = 0; j < VEC; j++) {
        float4 o4 = {xs[j].x * inv, xs[j].y * inv, xs[j].z * inv, xs[j].w * inv};
        out4[t + THREADS * j] = o4;
    }
}

} // anonymous namespace

extern "C" void kernel_launch(void* const* d_in, const int* in_sizes, int n_in,
                              void* d_out, int out_size)
{
    (void)n_in; (void)in_sizes;
    const float* w = (const float*)d_in[0];
    float* outp = (float*)d_out;
    int rows = out_size / N;            // 8192
    wdrop_kernel<<<rows, THREADS>>>(w, outp);
}